// round 1
// baseline (speedup 1.0000x reference)
#include <cuda_runtime.h>
#include <math.h>

#define B_ 64
#define S_ 1024
#define E_ 256

// Scratch for projected q, k, v (fp32). 3 x 64MB in device .bss — allowed
// (no runtime allocation).
__device__ float g_q[B_ * S_ * E_];
__device__ float g_k[B_ * S_ * E_];
__device__ float g_v[B_ * S_ * E_];

// ---------------- packed f32x2 helpers (FFMA2 path, sm_100+) ----------------
__device__ __forceinline__ unsigned long long pack2(float x, float y) {
    unsigned long long r;
    asm("mov.b64 %0, {%1,%2};" : "=l"(r) : "f"(x), "f"(y));
    return r;
}
__device__ __forceinline__ void unpack2(unsigned long long v, float &x, float &y) {
    asm("mov.b64 {%0,%1}, %2;" : "=f"(x), "=f"(y) : "l"(v));
}
__device__ __forceinline__ void ffma2(unsigned long long &d, unsigned long long a,
                                      unsigned long long b) {
    asm("fma.rn.f32x2 %0, %1, %2, %0;" : "+l"(d) : "l"(a), "l"(b));
}
__device__ __forceinline__ unsigned long long mul2(unsigned long long a,
                                                   unsigned long long b) {
    unsigned long long d;
    asm("mul.rn.f32x2 %0, %1, %2;" : "=l"(d) : "l"(a), "l"(b));
    return d;
}

union V4U {
    float4 f4;
    float f[4];
    unsigned long long u2[2];
};

// ============================================================================
// Kernel 1: QKV projection.  Y = X @ W + b for W in {Wq, Wk, Wv} (blockIdx.z).
// X: [65536, 256] row-major, W: [256, 256] row-major.
// Tile: BM=64 rows x full N=256 cols, BK=16.  256 threads, micro-tile 4x16.
// ============================================================================
__global__ __launch_bounds__(256) void proj_kernel(
    const float* __restrict__ x,
    const float* __restrict__ Wq, const float* __restrict__ bq,
    const float* __restrict__ Wk, const float* __restrict__ bk,
    const float* __restrict__ Wv, const float* __restrict__ bv) {
    __shared__ float As[64 * 16];
    __shared__ float Bs[16 * 256];

    const float* W;
    const float* bias;
    float* out;
    if (blockIdx.z == 0)      { W = Wq; bias = bq; out = g_q; }
    else if (blockIdx.z == 1) { W = Wk; bias = bk; out = g_k; }
    else                      { W = Wv; bias = bv; out = g_v; }

    const int tid = threadIdx.x;
    const int tx = tid & 15, ty = tid >> 4;
    const int m0 = blockIdx.x * 64;
    const int c0 = tx * 16;   // 16 output cols per thread
    const int r0 = ty * 4;    // 4 output rows per thread

    unsigned long long acc[4][8];
#pragma unroll
    for (int i = 0; i < 4; i++)
#pragma unroll
        for (int j = 0; j < 8; j++) acc[i][j] = 0ull;

    const int lrow = tid >> 2;
    const int lc4 = (tid & 3) * 4;

    for (int k0 = 0; k0 < 256; k0 += 16) {
        __syncthreads();
        // load X tile [64 x 16]
        *(float4*)&As[lrow * 16 + lc4] =
            *(const float4*)&x[(m0 + lrow) * 256 + k0 + lc4];
        // load W tile [16 x 256]
#pragma unroll
        for (int p = 0; p < 4; p++) {
            int idx = tid * 4 + p * 1024;
            int rr = idx >> 8, cc = idx & 255;
            *(float4*)&Bs[rr * 256 + cc] =
                *(const float4*)&W[(k0 + rr) * 256 + cc];
        }
        __syncthreads();

#pragma unroll
        for (int kk = 0; kk < 16; kk++) {
            unsigned long long av[4];
#pragma unroll
            for (int i = 0; i < 4; i++) {
                float a = As[(r0 + i) * 16 + kk];
                av[i] = pack2(a, a);
            }
            V4U bvv[4];
#pragma unroll
            for (int j = 0; j < 4; j++)
                bvv[j].f4 = *(const float4*)&Bs[kk * 256 + c0 + 4 * j];
#pragma unroll
            for (int i = 0; i < 4; i++)
#pragma unroll
                for (int j = 0; j < 4; j++) {
                    ffma2(acc[i][2 * j],     av[i], bvv[j].u2[0]);
                    ffma2(acc[i][2 * j + 1], av[i], bvv[j].u2[1]);
                }
        }
    }

    // epilogue: + bias, store
#pragma unroll
    for (int j = 0; j < 4; j++) {
        float4 bb = *(const float4*)&bias[c0 + 4 * j];
#pragma unroll
        for (int i = 0; i < 4; i++) {
            float o0, o1, o2, o3;
            unpack2(acc[i][2 * j], o0, o1);
            unpack2(acc[i][2 * j + 1], o2, o3);
            float4 res = make_float4(o0 + bb.x, o1 + bb.y, o2 + bb.z, o3 + bb.w);
            *(float4*)&out[(m0 + r0 + i) * 256 + c0 + 4 * j] = res;
        }
    }
}

// ============================================================================
// Kernel 2: flash-style attention.  One CTA = (batch b, 64-query tile).
// SMEM: sQT [256][64] (Q transposed, persistent), sK [64][257] (pad kills
// conflicts), sV [64][256], sPT [64][64] (P transposed, XOR-swizzled).
// 256 threads: tx=col-group (scores) / d-group (AV), ty=row-group.
// ============================================================================
#define SQT_OFF 0
#define SK_OFF  (256 * 64)
#define SV_OFF  (SK_OFF + 64 * 257)
#define SPT_OFF (SV_OFF + 64 * 256)
#define SMEM_FLOATS (SPT_OFF + 64 * 64)   // 53312 floats = 213248 bytes

__global__ __launch_bounds__(256) void attn_kernel(float* __restrict__ out) {
    extern __shared__ float sm[];
    float* sQT = sm + SQT_OFF;
    float* sK  = sm + SK_OFF;
    float* sV  = sm + SV_OFF;
    float* sPT = sm + SPT_OFF;

    const int tid = threadIdx.x;
    const int tx = tid & 15, ty = tid >> 4;
    const int b = blockIdx.y;
    const int q0 = blockIdx.x * 64;
    const int r0 = ty * 4;    // 4 query rows per thread
    const int c0 = tx * 4;    // 4 key cols per thread (scores)
    const int d0 = tx * 16;   // 16 output dims per thread (AV)

    // ---- load Q tile transposed: sQT[e][t] = q[b][q0+t][e] ----
    {
        const int t = tid & 63;
        const int ebase = (tid >> 6) * 4;
        const float* qsrc = g_q + (((unsigned)b << 10) + q0 + t) * 256;
#pragma unroll
        for (int p = 0; p < 16; p++) {
            int e = ebase + p * 16;
            float4 v = *(const float4*)&qsrc[e];
            sQT[(e + 0) * 64 + t] = v.x;
            sQT[(e + 1) * 64 + t] = v.y;
            sQT[(e + 2) * 64 + t] = v.z;
            sQT[(e + 3) * 64 + t] = v.w;
        }
    }

    unsigned long long accO[4][8];
#pragma unroll
    for (int i = 0; i < 4; i++)
#pragma unroll
        for (int j = 0; j < 8; j++) accO[i][j] = 0ull;
    float mrow[4], lrow[4];
#pragma unroll
    for (int i = 0; i < 4; i++) { mrow[i] = -3.0e38f; lrow[i] = 0.0f; }

    for (int kt = 0; kt < 16; kt++) {
        __syncthreads();   // prev AV done (and Q transpose done on first iter)

        // ---- load K (padded rows) and V tiles, coalesced ----
        const float* ksrc = g_k + ((((unsigned)b << 10) + kt * 64)) * 256;
        const float* vsrc = g_v + ((((unsigned)b << 10) + kt * 64)) * 256;
#pragma unroll
        for (int p = 0; p < 16; p++) {
            int idx = tid * 4 + p * 1024;
            int row = idx >> 8, e = idx & 255;
            float4 kv = *(const float4*)&ksrc[row * 256 + e];
            sK[row * 257 + e + 0] = kv.x;
            sK[row * 257 + e + 1] = kv.y;
            sK[row * 257 + e + 2] = kv.z;
            sK[row * 257 + e + 3] = kv.w;
            *(float4*)&sV[row * 256 + e] = *(const float4*)&vsrc[row * 256 + e];
        }
        __syncthreads();

        // ---- scores: S[c][r] = sum_e q[r][e] * k[c][e], rows packed in pairs ----
        unsigned long long accS[4][2] = {};
#pragma unroll 8
        for (int e = 0; e < 256; e++) {
            V4U a;
            a.f4 = *(const float4*)&sQT[e * 64 + r0];
#pragma unroll
            for (int c = 0; c < 4; c++) {
                float kv = sK[(c0 + c) * 257 + e];
                unsigned long long bb = pack2(kv, kv);
                ffma2(accS[c][0], a.u2[0], bb);
                ffma2(accS[c][1], a.u2[1], bb);
            }
        }
        float s[4][4];  // s[c][i] = score(row r0+i, col c0+c)
#pragma unroll
        for (int c = 0; c < 4; c++) {
            unpack2(accS[c][0], s[c][0], s[c][1]);
            unpack2(accS[c][1], s[c][2], s[c][3]);
        }

        // ---- online softmax (row stats shared by the 16 tx lanes of a ty group) ----
        float p_[4][4];
#pragma unroll
        for (int i = 0; i < 4; i++) {
            float mx = fmaxf(fmaxf(s[0][i], s[1][i]), fmaxf(s[2][i], s[3][i]));
#pragma unroll
            for (int off = 8; off > 0; off >>= 1)
                mx = fmaxf(mx, __shfl_xor_sync(0xffffffffu, mx, off));
            float mnew = fmaxf(mrow[i], mx);
            float corr = __expf(mrow[i] - mnew);
            float sum = 0.0f;
#pragma unroll
            for (int c = 0; c < 4; c++) {
                float pv = __expf(s[c][i] - mnew);
                p_[c][i] = pv;
                sum += pv;
            }
#pragma unroll
            for (int off = 8; off > 0; off >>= 1)
                sum += __shfl_xor_sync(0xffffffffu, sum, off);
            lrow[i] = lrow[i] * corr + sum;
            mrow[i] = mnew;
            unsigned long long cc = pack2(corr, corr);
#pragma unroll
            for (int j = 0; j < 8; j++) accO[i][j] = mul2(accO[i][j], cc);
        }

        // ---- store P transposed + XOR-swizzled: sPT[key][(ty ^ (key&15))*4 ..] ----
#pragma unroll
        for (int c = 0; c < 4; c++) {
            int key = c0 + c;
            int g = ty ^ (key & 15);
            *(float4*)&sPT[key * 64 + g * 4] =
                make_float4(p_[c][0], p_[c][1], p_[c][2], p_[c][3]);
        }
        __syncthreads();

        // ---- AV: O[r][d] += sum_t P[r][t] * V[t][d] ----
#pragma unroll 4
        for (int t = 0; t < 64; t++) {
            V4U pv;
            int g = ty ^ (t & 15);
            pv.f4 = *(const float4*)&sPT[t * 64 + g * 4];
            V4U v4[4];
#pragma unroll
            for (int j = 0; j < 4; j++)
                v4[j].f4 = *(const float4*)&sV[t * 256 + d0 + 4 * j];
#pragma unroll
            for (int i = 0; i < 4; i++) {
                unsigned long long pp = pack2(pv.f[i], pv.f[i]);
#pragma unroll
                for (int j = 0; j < 4; j++) {
                    ffma2(accO[i][2 * j],     pp, v4[j].u2[0]);
                    ffma2(accO[i][2 * j + 1], pp, v4[j].u2[1]);
                }
            }
        }
    }

    // ---- epilogue: O / l -> ctx ----
#pragma unroll
    for (int i = 0; i < 4; i++) {
        float inv = 1.0f / lrow[i];
        float* dst = out + (((unsigned)b << 10) + q0 + r0 + i) * 256 + d0;
#pragma unroll
        for (int j = 0; j < 4; j++) {
            float o0, o1, o2, o3;
            unpack2(accO[i][2 * j], o0, o1);
            unpack2(accO[i][2 * j + 1], o2, o3);
            *(float4*)&dst[4 * j] = make_float4(o0 * inv, o1 * inv, o2 * inv, o3 * inv);
        }
    }
}

// ============================================================================
extern "C" void kernel_launch(void* const* d_in, const int* in_sizes, int n_in,
                              void* d_out, int out_size) {
    const float* x  = (const float*)d_in[0];
    const float* Wq = (const float*)d_in[1];
    const float* bq = (const float*)d_in[2];
    const float* Wk = (const float*)d_in[3];
    const float* bk = (const float*)d_in[4];
    const float* Wv = (const float*)d_in[5];
    const float* bv = (const float*)d_in[6];
    float* out = (float*)d_out;

    // idempotent, host-side, not a stream op — safe under graph capture
    cudaFuncSetAttribute(attn_kernel, cudaFuncAttributeMaxDynamicSharedMemorySize,
                         SMEM_FLOATS * (int)sizeof(float));

    // QKV projections: 1024 row-tiles x 3 weight matrices
    proj_kernel<<<dim3(1024, 1, 3), 256>>>(x, Wq, bq, Wk, bk, Wv, bv);

    // Attention: 16 query tiles x 64 batches
    attn_kernel<<<dim3(16, 64), 256, SMEM_FLOATS * (int)sizeof(float)>>>(out);
}

// round 2
// speedup vs baseline: 1.9312x; 1.9312x over previous
#include <cuda_runtime.h>
#include <math.h>

#define B_ 64
#define S_ 1024
#define E_ 256

__device__ float g_q[B_ * S_ * E_];
__device__ float g_k[B_ * S_ * E_];
__device__ float g_v[B_ * S_ * E_];

// ---------------- packed f32x2 helpers (FFMA2 path, sm_100+) ----------------
__device__ __forceinline__ unsigned long long pack2(float x, float y) {
    unsigned long long r;
    asm("mov.b64 %0, {%1,%2};" : "=l"(r) : "f"(x), "f"(y));
    return r;
}
__device__ __forceinline__ void unpack2(unsigned long long v, float &x, float &y) {
    asm("mov.b64 {%0,%1}, %2;" : "=f"(x), "=f"(y) : "l"(v));
}
__device__ __forceinline__ void ffma2(unsigned long long &d, unsigned long long a,
                                      unsigned long long b) {
    asm("fma.rn.f32x2 %0, %1, %2, %0;" : "+l"(d) : "l"(a), "l"(b));
}
__device__ __forceinline__ unsigned long long mul2(unsigned long long a,
                                                   unsigned long long b) {
    unsigned long long d;
    asm("mul.rn.f32x2 %0, %1, %2;" : "=l"(d) : "l"(a), "l"(b));
    return d;
}

union V4U {
    float4 f4;
    float f[4];
    unsigned long long u2[2];
};

// ============================================================================
// Kernel 1: QKV projection.  Y = X @ W + b.
// Tile: BM=128 x BN=128, BK=16. 256 threads, 8x8 micro-tile.
// A transposed in SMEM (float4 column reads), B XOR-swizzled (granule g ^= (g>>3)&3).
// grid = (512, 2, 3): x = row tile, y = col half, z = which W.
// ============================================================================
__global__ __launch_bounds__(256) void proj_kernel(
    const float* __restrict__ x,
    const float* __restrict__ Wq, const float* __restrict__ bq,
    const float* __restrict__ Wk, const float* __restrict__ bk,
    const float* __restrict__ Wv, const float* __restrict__ bv) {
    __shared__ float AsT[16 * 128];   // [k][row]
    __shared__ float Bs[16 * 128];    // [k][col] XOR-swizzled granules

    const float* W;
    const float* bias;
    float* out;
    if (blockIdx.z == 0)      { W = Wq; bias = bq; out = g_q; }
    else if (blockIdx.z == 1) { W = Wk; bias = bk; out = g_k; }
    else                      { W = Wv; bias = bv; out = g_v; }

    const int tid = threadIdx.x;
    const int tx = tid & 15, ty = tid >> 4;
    const int m0 = blockIdx.x * 128;
    const int n0 = blockIdx.y * 128;
    const int r0 = ty * 8;          // 8 rows per thread
    const int cl = tx * 8;          // 8 cols per thread (local)

    // Bs read granules for this thread (swizzled), hoisted
    const int gb0 = 2 * tx, gb1 = 2 * tx + 1;
    const int gs0 = gb0 ^ ((gb0 >> 3) & 3);
    const int gs1 = gb1 ^ ((gb1 >> 3) & 3);

    unsigned long long acc[8][4];
#pragma unroll
    for (int i = 0; i < 8; i++)
#pragma unroll
        for (int j = 0; j < 4; j++) acc[i][j] = 0ull;

    const int lrow = tid >> 1;           // X loader: row
    const int lkh = (tid & 1) * 8;       // k half

    for (int k0 = 0; k0 < 256; k0 += 16) {
        __syncthreads();
        // X tile [128 x 16] -> AsT[k][row] (scalar transpose stores)
        {
            const float* xs = &x[(m0 + lrow) * 256 + k0 + lkh];
            float4 a0 = *(const float4*)&xs[0];
            float4 a1 = *(const float4*)&xs[4];
            AsT[(lkh + 0) * 128 + lrow] = a0.x;
            AsT[(lkh + 1) * 128 + lrow] = a0.y;
            AsT[(lkh + 2) * 128 + lrow] = a0.z;
            AsT[(lkh + 3) * 128 + lrow] = a0.w;
            AsT[(lkh + 4) * 128 + lrow] = a1.x;
            AsT[(lkh + 5) * 128 + lrow] = a1.y;
            AsT[(lkh + 6) * 128 + lrow] = a1.z;
            AsT[(lkh + 7) * 128 + lrow] = a1.w;
        }
        // W tile [16 x 128] -> Bs swizzled
#pragma unroll
        for (int p = 0; p < 2; p++) {
            int idx = tid * 4 + p * 1024;
            int rr = idx >> 7, cc = idx & 127;
            int g = cc >> 2;
            int gsw = g ^ ((g >> 3) & 3);
            *(float4*)&Bs[rr * 128 + gsw * 4] =
                *(const float4*)&W[(k0 + rr) * 256 + n0 + cc];
        }
        __syncthreads();

#pragma unroll
        for (int kk = 0; kk < 16; kk++) {
            V4U a0, a1;
            a0.f4 = *(const float4*)&AsT[kk * 128 + r0];
            a1.f4 = *(const float4*)&AsT[kk * 128 + r0 + 4];
            V4U b0, b1;
            b0.f4 = *(const float4*)&Bs[kk * 128 + gs0 * 4];
            b1.f4 = *(const float4*)&Bs[kk * 128 + gs1 * 4];
#pragma unroll
            for (int i = 0; i < 8; i++) {
                float av = (i < 4) ? a0.f[i] : a1.f[i - 4];
                unsigned long long ad = pack2(av, av);
                ffma2(acc[i][0], ad, b0.u2[0]);
                ffma2(acc[i][1], ad, b0.u2[1]);
                ffma2(acc[i][2], ad, b1.u2[0]);
                ffma2(acc[i][3], ad, b1.u2[1]);
            }
        }
    }

    // epilogue: + bias, store
    float4 bb0 = *(const float4*)&bias[n0 + cl];
    float4 bb1 = *(const float4*)&bias[n0 + cl + 4];
#pragma unroll
    for (int i = 0; i < 8; i++) {
        float o0, o1, o2, o3, o4, o5, o6, o7;
        unpack2(acc[i][0], o0, o1);
        unpack2(acc[i][1], o2, o3);
        unpack2(acc[i][2], o4, o5);
        unpack2(acc[i][3], o6, o7);
        float* dst = &out[(m0 + r0 + i) * 256 + n0 + cl];
        *(float4*)&dst[0] = make_float4(o0 + bb0.x, o1 + bb0.y, o2 + bb0.z, o3 + bb0.w);
        *(float4*)&dst[4] = make_float4(o4 + bb1.x, o5 + bb1.y, o6 + bb1.z, o7 + bb1.w);
    }
}

// ============================================================================
// Kernel 2: flash attention, FMA-bound layout.
// SMEM: sQT[e][q] 64KB, sKT[e][k] 64KB (transposed per tile), sV[t][d] 64KB
// (XOR-swizzled granules), sP[q][t] (pitch 72), sM/sL/sCorr[64].
// Scores map: 16 tx (4 keys) x 16 ty (4 rows).  AV map: 32 tx (8 d) x 8 ty (8 rows).
// ============================================================================
#define SQT_OFF 0
#define SKT_OFF (256 * 64)
#define SV_OFF  (SKT_OFF + 256 * 64)
#define SP_OFF  (SV_OFF + 64 * 256)
#define SM_OFF  (SP_OFF + 64 * 72)
#define SL_OFF  (SM_OFF + 64)
#define SC_OFF  (SL_OFF + 64)
#define SMEM_FLOATS (SC_OFF + 64)   // 53952 floats = 215808 bytes

__global__ __launch_bounds__(256) void attn_kernel(float* __restrict__ out) {
    extern __shared__ float sm[];
    float* sQT = sm + SQT_OFF;
    float* sKT = sm + SKT_OFF;
    float* sV  = sm + SV_OFF;
    float* sP  = sm + SP_OFF;
    float* sM  = sm + SM_OFF;
    float* sL  = sm + SL_OFF;
    float* sC  = sm + SC_OFF;

    const int tid = threadIdx.x;
    const int b = blockIdx.y;
    const int q0 = blockIdx.x * 64;

    // scores mapping
    const int txs = tid & 15, tys = tid >> 4;
    const int c0s = txs * 4, r0s = tys * 4;
    // AV mapping
    const int txa = tid & 31, tya = tid >> 5;
    const int d0 = txa * 8, r0a = tya * 8;
    // V read granules (swizzled), hoisted
    const int gv0 = 2 * txa, gv1 = 2 * txa + 1;
    const int gvs0 = gv0 ^ ((gv0 >> 3) & 7);
    const int gvs1 = gv1 ^ ((gv1 >> 3) & 7);
    // transpose loader mapping
    const int tt_ = tid & 63;
    const int eb = (tid >> 6) * 4;

    // ---- Q transposed into sQT (once) ----
    {
        const float* qsrc = g_q + (((unsigned)b << 10) + q0 + tt_) * 256;
#pragma unroll
        for (int p = 0; p < 16; p++) {
            int e = eb + p * 16;
            float4 v = *(const float4*)&qsrc[e];
            sQT[(e + 0) * 64 + tt_] = v.x;
            sQT[(e + 1) * 64 + tt_] = v.y;
            sQT[(e + 2) * 64 + tt_] = v.z;
            sQT[(e + 3) * 64 + tt_] = v.w;
        }
    }
    if (tid < 64) { sM[tid] = -3.0e38f; sL[tid] = 0.0f; }

    unsigned long long accO[8][4];
#pragma unroll
    for (int i = 0; i < 8; i++)
#pragma unroll
        for (int j = 0; j < 4; j++) accO[i][j] = 0ull;

    for (int kt = 0; kt < 16; kt++) {
        __syncthreads();   // prev AV done; K/V/P free (also covers Q/init on iter 0)

        // ---- K transposed into sKT ----
        {
            const float* ksrc = g_k + (((unsigned)b << 10) + kt * 64 + tt_) * 256;
#pragma unroll
            for (int p = 0; p < 16; p++) {
                int e = eb + p * 16;
                float4 v = *(const float4*)&ksrc[e];
                sKT[(e + 0) * 64 + tt_] = v.x;
                sKT[(e + 1) * 64 + tt_] = v.y;
                sKT[(e + 2) * 64 + tt_] = v.z;
                sKT[(e + 3) * 64 + tt_] = v.w;
            }
        }
        // ---- V coalesced, XOR-swizzled granules ----
        {
            const float* vsrc = g_v + (((unsigned)b << 10) + kt * 64) * 256;
#pragma unroll
            for (int p = 0; p < 16; p++) {
                int idx = tid * 4 + p * 1024;
                int row = idx >> 8, e = idx & 255;
                int g = e >> 2;
                int gsw = g ^ ((g >> 3) & 7);
                *(float4*)&sV[row * 256 + gsw * 4] = *(const float4*)&vsrc[row * 256 + e];
            }
        }
        __syncthreads();

        // ---- scores: float4 Q (4 rows) x float4 K (4 keys) ----
        unsigned long long accS[4][2];
#pragma unroll
        for (int c = 0; c < 4; c++) { accS[c][0] = 0ull; accS[c][1] = 0ull; }
#pragma unroll 8
        for (int e = 0; e < 256; e++) {
            V4U a, kf;
            a.f4 = *(const float4*)&sQT[e * 64 + r0s];
            kf.f4 = *(const float4*)&sKT[e * 64 + c0s];
#pragma unroll
            for (int c = 0; c < 4; c++) {
                unsigned long long bb = pack2(kf.f[c], kf.f[c]);
                ffma2(accS[c][0], a.u2[0], bb);
                ffma2(accS[c][1], a.u2[1], bb);
            }
        }
        float s[4][4];
#pragma unroll
        for (int c = 0; c < 4; c++) {
            unpack2(accS[c][0], s[c][0], s[c][1]);
            unpack2(accS[c][1], s[c][2], s[c][3]);
        }

        // ---- online softmax (reduce over 16 txs lanes) ----
        float p_[4][4];
#pragma unroll
        for (int i = 0; i < 4; i++) {
            int row = r0s + i;
            float mx = fmaxf(fmaxf(s[0][i], s[1][i]), fmaxf(s[2][i], s[3][i]));
#pragma unroll
            for (int off = 8; off > 0; off >>= 1)
                mx = fmaxf(mx, __shfl_xor_sync(0xffffffffu, mx, off));
            float mold = sM[row];
            float mnew = fmaxf(mold, mx);
            float sum = 0.0f;
#pragma unroll
            for (int c = 0; c < 4; c++) {
                float pv = __expf(s[c][i] - mnew);
                p_[c][i] = pv;
                sum += pv;
            }
#pragma unroll
            for (int off = 8; off > 0; off >>= 1)
                sum += __shfl_xor_sync(0xffffffffu, sum, off);
            if (txs == 0) {
                float corr = __expf(mold - mnew);
                sM[row] = mnew;
                sC[row] = corr;
                sL[row] = sL[row] * corr + sum;
            }
        }
        // ---- store P row-major (pitch 72) ----
#pragma unroll
        for (int i = 0; i < 4; i++)
            *(float4*)&sP[(r0s + i) * 72 + c0s] =
                make_float4(p_[0][i], p_[1][i], p_[2][i], p_[3][i]);
        __syncthreads();

        // ---- AV: rescale accO then accumulate 8 rows x 8 dims ----
#pragma unroll
        for (int i = 0; i < 8; i++) {
            float cc = sC[r0a + i];
            unsigned long long c2 = pack2(cc, cc);
#pragma unroll
            for (int j = 0; j < 4; j++) accO[i][j] = mul2(accO[i][j], c2);
        }
#pragma unroll 2
        for (int t0 = 0; t0 < 64; t0 += 4) {
            V4U pr[8];
#pragma unroll
            for (int i = 0; i < 8; i++)
                pr[i].f4 = *(const float4*)&sP[(r0a + i) * 72 + t0];
#pragma unroll
            for (int ttk = 0; ttk < 4; ttk++) {
                int t = t0 + ttk;
                V4U v0, v1;
                v0.f4 = *(const float4*)&sV[t * 256 + gvs0 * 4];
                v1.f4 = *(const float4*)&sV[t * 256 + gvs1 * 4];
#pragma unroll
                for (int i = 0; i < 8; i++) {
                    unsigned long long pp = pack2(pr[i].f[ttk], pr[i].f[ttk]);
                    ffma2(accO[i][0], pp, v0.u2[0]);
                    ffma2(accO[i][1], pp, v0.u2[1]);
                    ffma2(accO[i][2], pp, v1.u2[0]);
                    ffma2(accO[i][3], pp, v1.u2[1]);
                }
            }
        }
    }

    // ---- epilogue ----
#pragma unroll
    for (int i = 0; i < 8; i++) {
        int row = r0a + i;
        float inv = 1.0f / sL[row];
        float* dst = out + (((unsigned)b << 10) + q0 + row) * 256 + d0;
        float o0, o1, o2, o3, o4, o5, o6, o7;
        unpack2(accO[i][0], o0, o1);
        unpack2(accO[i][1], o2, o3);
        unpack2(accO[i][2], o4, o5);
        unpack2(accO[i][3], o6, o7);
        *(float4*)&dst[0] = make_float4(o0 * inv, o1 * inv, o2 * inv, o3 * inv);
        *(float4*)&dst[4] = make_float4(o4 * inv, o5 * inv, o6 * inv, o7 * inv);
    }
}

// ============================================================================
extern "C" void kernel_launch(void* const* d_in, const int* in_sizes, int n_in,
                              void* d_out, int out_size) {
    const float* x  = (const float*)d_in[0];
    const float* Wq = (const float*)d_in[1];
    const float* bq = (const float*)d_in[2];
    const float* Wk = (const float*)d_in[3];
    const float* bk = (const float*)d_in[4];
    const float* Wv = (const float*)d_in[5];
    const float* bv = (const float*)d_in[6];
    float* out = (float*)d_out;

    cudaFuncSetAttribute(attn_kernel, cudaFuncAttributeMaxDynamicSharedMemorySize,
                         SMEM_FLOATS * (int)sizeof(float));

    proj_kernel<<<dim3(512, 2, 3), 256>>>(x, Wq, bq, Wk, bk, Wv, bv);
    attn_kernel<<<dim3(16, 64), 256, SMEM_FLOATS * (int)sizeof(float)>>>(out);
}

// round 4
// speedup vs baseline: 4.7282x; 2.4483x over previous
#include <cuda_runtime.h>
#include <cuda_bf16.h>
#include <math.h>
#include <stdint.h>

#define B_ 64
#define S_ 1024
#define E_ 256
#define NQK (64ull * 1024 * 256)      // 16.78M elems
#define NS  (64ull * 1024 * 1024)     // 67.1M elems

// -------------------- device scratch (static .bss, no runtime alloc) --------
__device__ float          g_v  [NQK];                 // v fp32 [b][t][d]
__device__ __nv_bfloat16  g_xh [NQK], g_xl [NQK];     // x split [m][e]
__device__ __nv_bfloat16  g_wth[3 * 256 * 256], g_wtl[3 * 256 * 256];  // W^T split [z][n][e]
__device__ __nv_bfloat16  g_qh [NQK], g_ql[NQK];
__device__ __nv_bfloat16  g_kh [NQK], g_kl[NQK];
__device__ __nv_bfloat16  g_vth[NQK], g_vtl[NQK];     // vT [b][d][t]
__device__ float          g_s  [NS];                  // scores fp32; later P hi/lo bf16 in place

union BP8 { __nv_bfloat16 b[8]; uint4 u; };
union BP4 { __nv_bfloat16 b[4]; uint2 u; };

// ---------------- base-target PTX helpers (sm_80+ features only) ------------
__device__ __forceinline__ uint32_t smem_u32(const void* p) {
    uint32_t a;
    asm("{ .reg .u64 t; cvta.to.shared.u64 t, %1; cvt.u32.u64 %0, t; }" : "=r"(a) : "l"(p));
    return a;
}
__device__ __forceinline__ void cpa16(uint32_t saddr, const void* g) {
    asm volatile("cp.async.cg.shared.global [%0], [%1], 16;" :: "r"(saddr), "l"(g));
}
#define CPA_COMMIT() asm volatile("cp.async.commit_group;" ::: "memory")
#define CPA_WAIT1()  asm volatile("cp.async.wait_group 1;" ::: "memory")

__device__ __forceinline__ void ldsm_x4(uint32_t* r, uint32_t addr) {
    asm volatile("ldmatrix.sync.aligned.m8n8.x4.shared.b16 {%0,%1,%2,%3}, [%4];"
                 : "=r"(r[0]), "=r"(r[1]), "=r"(r[2]), "=r"(r[3]) : "r"(addr));
}
__device__ __forceinline__ void mma16816(float* c, const uint32_t* a, const uint32_t* b) {
    asm volatile(
        "mma.sync.aligned.m16n8k16.row.col.f32.bf16.bf16.f32 "
        "{%0,%1,%2,%3}, {%4,%5,%6,%7}, {%8,%9}, {%0,%1,%2,%3};"
        : "+f"(c[0]), "+f"(c[1]), "+f"(c[2]), "+f"(c[3])
        : "r"(a[0]), "r"(a[1]), "r"(a[2]), "r"(a[3]), "r"(b[0]), "r"(b[1]));
}

__device__ __forceinline__ void store_hilo2(__nv_bfloat16* dh, __nv_bfloat16* dl,
                                            float a, float b) {
    __nv_bfloat16 ha = __float2bfloat16_rn(a), hb = __float2bfloat16_rn(b);
    __nv_bfloat16 la = __float2bfloat16_rn(a - __bfloat162float(ha));
    __nv_bfloat16 lb = __float2bfloat16_rn(b - __bfloat162float(hb));
    __nv_bfloat162 hp; hp.x = ha; hp.y = hb;
    __nv_bfloat162 lp; lp.x = la; lp.y = lb;
    *(__nv_bfloat162*)dh = hp;
    *(__nv_bfloat162*)dl = lp;
}

// ============================================================================
// Triple-bf16 HMMA GEMM: D = Ah.Bh^T + Ah.Bl^T + Al.Bh^T  (fp32 accum)
// A: [rows][lda] k-major; B: [NTOT-rows][ldb] k-major ("row.col" mma).
// CTA tile 128x128, k-chunk 64, 8 warps (4 m x 2 n), warp tile 32x64.
// SMEM: 2 stages x 4 matrices x (128 rows x 128B swizzled) = 128KB.
// EPI 0: C fp32 [m][NTOT] (+z*cBatch).  EPI 1: proj epilogue (bias + split).
// ============================================================================
#define GSM_BYTES (2 * 65536 + 128)

template<int NCH, int NTOT, int EPI>
__global__ __launch_bounds__(256) void gemm3_mma(
    const __nv_bfloat16* __restrict__ Ah_, const __nv_bfloat16* __restrict__ Al_,
    const __nv_bfloat16* __restrict__ Bh_, const __nv_bfloat16* __restrict__ Bl_,
    float* __restrict__ C,
    const float* __restrict__ bq, const float* __restrict__ bk,
    const float* __restrict__ bv,
    long long aBatch, long long bBatch, long long cBatch, int lda, int ldb) {
    extern __shared__ char dsm[];
    char* sb = (char*)(((uintptr_t)dsm + 127) & ~(uintptr_t)127);
    const uint32_t sbase = smem_u32(sb);

    const int tid = threadIdx.x;
    const int wid = tid >> 5, lane = tid & 31;
    const int z = blockIdx.z;
    const int m0 = blockIdx.x * 128, n0 = blockIdx.y * 128;

    const __nv_bfloat16* gA[2] = { Ah_ + (size_t)z * aBatch + (size_t)m0 * lda,
                                   Al_ + (size_t)z * aBatch + (size_t)m0 * lda };
    const __nv_bfloat16* gB[2] = { Bh_ + (size_t)z * bBatch + (size_t)n0 * ldb,
                                   Bl_ + (size_t)z * bBatch + (size_t)n0 * ldb };

    const int lrow = tid >> 3, lkg = tid & 7;   // loader: 8 threads per 128B row

    // ldmatrix lane geometry
    const int wm = wid & 3, wn = wid >> 2;
    const int li = lane >> 3, lr = lane & 7;
    const int arow = wm * 32 + (li & 1) * 8 + lr;
    const int brow = wn * 64 + (li & 1) * 8 + lr;
    const int kgh = li >> 1;                    // 0/1: k half within k16

    float acc[2][8][4];
#pragma unroll
    for (int im = 0; im < 2; im++)
#pragma unroll
        for (int j = 0; j < 8; j++)
#pragma unroll
            for (int q = 0; q < 4; q++) acc[im][j][q] = 0.0f;

#define LOAD_STAGE(kc, st) do {                                                  \
        uint32_t s0_ = sbase + (st) * 65536;                                     \
        _Pragma("unroll")                                                        \
        for (int m_ = 0; m_ < 4; m_++) {                                         \
            const __nv_bfloat16* src_ = (m_ < 2) ? gA[m_] : gB[m_ - 2];          \
            int ld_ = (m_ < 2) ? lda : ldb;                                      \
            _Pragma("unroll")                                                    \
            for (int p_ = 0; p_ < 4; p_++) {                                     \
                int row_ = lrow + p_ * 32;                                       \
                cpa16(s0_ + m_ * 16384 + row_ * 128 + ((lkg ^ (row_ & 7)) << 4), \
                      src_ + (size_t)row_ * ld_ + (kc) * 64 + lkg * 8);          \
            }                                                                    \
        }                                                                        \
    } while (0)

    LOAD_STAGE(0, 0); CPA_COMMIT();
    LOAD_STAGE(1, 1); CPA_COMMIT();

    for (int kc = 0; kc < NCH; kc++) {
        CPA_WAIT1();
        __syncthreads();
        const uint32_t s0 = sbase + (kc & 1) * 65536;
#pragma unroll
        for (int kt = 0; kt < 4; kt++) {
            const int kg = kt * 2 + kgh;
            uint32_t ah[2][4], al[2][4], bh[4][4], bl[4][4];
#pragma unroll
            for (int im = 0; im < 2; im++) {
                int m_l = arow + im * 16;
                uint32_t ad = s0 + m_l * 128 + ((kg ^ (m_l & 7)) << 4);
                ldsm_x4(ah[im], ad);
                ldsm_x4(al[im], ad + 16384);
            }
#pragma unroll
            for (int jn = 0; jn < 4; jn++) {
                int n_l = brow + jn * 16;
                uint32_t bd = s0 + 32768 + n_l * 128 + ((kg ^ (n_l & 7)) << 4);
                ldsm_x4(bh[jn], bd);
                ldsm_x4(bl[jn], bd + 16384);
            }
#pragma unroll
            for (int im = 0; im < 2; im++)
#pragma unroll
                for (int j8 = 0; j8 < 8; j8++) {
                    uint32_t bfh[2] = { bh[j8 >> 1][j8 & 1], bh[j8 >> 1][(j8 & 1) + 2] };
                    uint32_t bfl[2] = { bl[j8 >> 1][j8 & 1], bl[j8 >> 1][(j8 & 1) + 2] };
                    mma16816(acc[im][j8], ah[im], bfh);
                    mma16816(acc[im][j8], ah[im], bfl);
                    mma16816(acc[im][j8], al[im], bfh);
                }
        }
        __syncthreads();
        if (kc + 2 < NCH) LOAD_STAGE(kc + 2, kc & 1);
        CPA_COMMIT();
    }
#undef LOAD_STAGE

    // -------- epilogue --------
    const int erow = wm * 32 + (lane >> 2);
    const int ecol = wn * 64 + 2 * (lane & 3);
    if (EPI == 0) {
        float* Cb = C + (size_t)z * cBatch;
#pragma unroll
        for (int im = 0; im < 2; im++)
#pragma unroll
            for (int j8 = 0; j8 < 8; j8++) {
                int rr = m0 + erow + im * 16;
                int cc = n0 + ecol + j8 * 8;
                *(float2*)&Cb[(size_t)rr * NTOT + cc] =
                    make_float2(acc[im][j8][0], acc[im][j8][1]);
                *(float2*)&Cb[(size_t)(rr + 8) * NTOT + cc] =
                    make_float2(acc[im][j8][2], acc[im][j8][3]);
            }
    } else {
        const float* bias = (z == 0) ? bq : (z == 1) ? bk : bv;
#pragma unroll
        for (int im = 0; im < 2; im++)
#pragma unroll
            for (int j8 = 0; j8 < 8; j8++) {
                int rr = m0 + erow + im * 16;
                int cc = n0 + ecol + j8 * 8;
                float b0v = bias[cc], b1v = bias[cc + 1];
                float v00 = acc[im][j8][0] + b0v, v01 = acc[im][j8][1] + b1v;
                float v10 = acc[im][j8][2] + b0v, v11 = acc[im][j8][3] + b1v;
                if (z == 2) {
                    *(float2*)&g_v[(size_t)rr * 256 + cc] = make_float2(v00, v01);
                    *(float2*)&g_v[(size_t)(rr + 8) * 256 + cc] = make_float2(v10, v11);
                } else {
                    __nv_bfloat16* dh = (z == 0) ? g_qh : g_kh;
                    __nv_bfloat16* dl = (z == 0) ? g_ql : g_kl;
                    store_hilo2(dh + (size_t)rr * 256 + cc, dl + (size_t)rr * 256 + cc, v00, v01);
                    store_hilo2(dh + (size_t)(rr + 8) * 256 + cc, dl + (size_t)(rr + 8) * 256 + cc, v10, v11);
                }
            }
    }
}

// ============================================================================
// split x -> bf16 hi/lo
// ============================================================================
__global__ __launch_bounds__(256) void split_x_kernel(const float* __restrict__ x) {
    size_t i = ((size_t)blockIdx.x * 256 + threadIdx.x) * 4;
    float4 v = *(const float4*)&x[i];
    float f[4] = { v.x, v.y, v.z, v.w };
    BP4 hp, lp;
#pragma unroll
    for (int j = 0; j < 4; j++) {
        hp.b[j] = __float2bfloat16_rn(f[j]);
        lp.b[j] = __float2bfloat16_rn(f[j] - __bfloat162float(hp.b[j]));
    }
    *(uint2*)&g_xh[i] = hp.u;
    *(uint2*)&g_xl[i] = lp.u;
}

// ============================================================================
// transpose + split W (256x256, [e][n] -> [n][e] hi/lo), z = which W
// ============================================================================
__global__ __launch_bounds__(256) void splitT_w_kernel(
    const float* __restrict__ Wq, const float* __restrict__ Wk,
    const float* __restrict__ Wv) {
    __shared__ float ts[64 * 65];
    const float* W = (blockIdx.z == 0) ? Wq : (blockIdx.z == 1) ? Wk : Wv;
    const int e0 = blockIdx.x * 64, n0 = blockIdx.y * 64;
    const int tid = threadIdx.x;
    const size_t zo = (size_t)blockIdx.z * 65536;

#pragma unroll
    for (int p = 0; p < 4; p++) {
        int idx = tid + p * 256;
        int r = idx >> 4, c4 = idx & 15;
        float4 v = *(const float4*)&W[(size_t)(e0 + r) * 256 + n0 + c4 * 4];
        ts[r * 65 + c4 * 4 + 0] = v.x; ts[r * 65 + c4 * 4 + 1] = v.y;
        ts[r * 65 + c4 * 4 + 2] = v.z; ts[r * 65 + c4 * 4 + 3] = v.w;
    }
    __syncthreads();
#pragma unroll
    for (int p = 0; p < 2; p++) {
        int idx = tid + p * 256;
        int nl = idx >> 3, tc = idx & 7;
        BP8 hp, lp;
#pragma unroll
        for (int j = 0; j < 8; j++) {
            float v = ts[(tc * 8 + j) * 65 + nl];
            hp.b[j] = __float2bfloat16_rn(v);
            lp.b[j] = __float2bfloat16_rn(v - __bfloat162float(hp.b[j]));
        }
        size_t di = zo + (size_t)(n0 + nl) * 256 + e0 + tc * 8;
        *(uint4*)&g_wth[di] = hp.u;
        *(uint4*)&g_wtl[di] = lp.u;
    }
}

// ============================================================================
// transpose + split v -> vT hi/lo.  grid (16 t-tiles, 4 d-tiles, 64 b)
// ============================================================================
__global__ __launch_bounds__(256) void conv_vT_kernel() {
    __shared__ float ts[64 * 65];
    const int tid = threadIdx.x;
    const int t0 = blockIdx.x * 64, d0 = blockIdx.y * 64, b = blockIdx.z;

#pragma unroll
    for (int p = 0; p < 4; p++) {
        int idx = tid + p * 256;
        int r = idx >> 4, c4 = idx & 15;
        float4 v = *(const float4*)&g_v[((size_t)(b << 10) + t0 + r) * 256 + d0 + c4 * 4];
        ts[r * 65 + c4 * 4 + 0] = v.x; ts[r * 65 + c4 * 4 + 1] = v.y;
        ts[r * 65 + c4 * 4 + 2] = v.z; ts[r * 65 + c4 * 4 + 3] = v.w;
    }
    __syncthreads();
#pragma unroll
    for (int p = 0; p < 2; p++) {
        int idx = tid + p * 256;
        int dl = idx >> 3, tc = idx & 7;
        BP8 hp, lp;
#pragma unroll
        for (int j = 0; j < 8; j++) {
            float v = ts[(tc * 8 + j) * 65 + dl];
            hp.b[j] = __float2bfloat16_rn(v);
            lp.b[j] = __float2bfloat16_rn(v - __bfloat162float(hp.b[j]));
        }
        size_t di = ((size_t)b * 256 + d0 + dl) * 1024 + t0 + tc * 8;
        *(uint4*)&g_vth[di] = hp.u;
        *(uint4*)&g_vtl[di] = lp.u;
    }
}

// ============================================================================
// softmax + normalize + bf16 hi/lo split, IN PLACE over g_s rows.
// One CTA per row.  FMA-poly exp (MUFU throughput too low at 67M exps).
// ============================================================================
__device__ __forceinline__ float fast_exp(float x) {   // x <= 0
    float y = x * 1.4426950408889634f;
    float n = rintf(y);
    float t = (y - n) * 0.6931471805599453f;
    float p = 1.9841270e-4f;
    p = fmaf(p, t, 1.3888889e-3f);
    p = fmaf(p, t, 8.3333333e-3f);
    p = fmaf(p, t, 4.1666667e-2f);
    p = fmaf(p, t, 0.16666667f);
    p = fmaf(p, t, 0.5f);
    p = fmaf(p, t, 1.0f);
    p = fmaf(p, t, 1.0f);
    float r = __int_as_float(__float_as_int(p) + ((int)n << 23));
    return (x > -87.0f) ? r : 0.0f;
}

__global__ __launch_bounds__(256) void softmax_kernel(float* __restrict__ S) {
    __shared__ float red[8];
    const int tid = threadIdx.x;
    const int wid = tid >> 5, lane = tid & 31;
    float* rp = S + (size_t)blockIdx.x * 1024;

    float4 v = *(const float4*)(rp + tid * 4);
    float m4 = fmaxf(fmaxf(v.x, v.y), fmaxf(v.z, v.w));
#pragma unroll
    for (int off = 16; off > 0; off >>= 1)
        m4 = fmaxf(m4, __shfl_xor_sync(0xffffffffu, m4, off));
    if (lane == 0) red[wid] = m4;
    __syncthreads();
    float m = red[0];
#pragma unroll
    for (int i = 1; i < 8; i++) m = fmaxf(m, red[i]);
    __syncthreads();

    float e0 = fast_exp(v.x - m), e1 = fast_exp(v.y - m);
    float e2 = fast_exp(v.z - m), e3 = fast_exp(v.w - m);
    float s4 = (e0 + e1) + (e2 + e3);
#pragma unroll
    for (int off = 16; off > 0; off >>= 1)
        s4 += __shfl_xor_sync(0xffffffffu, s4, off);
    if (lane == 0) red[wid] = s4;
    __syncthreads();
    float sum = red[0];
#pragma unroll
    for (int i = 1; i < 8; i++) sum += red[i];
    float pinv = __frcp_rn(sum);

    float pv[4] = { e0 * pinv, e1 * pinv, e2 * pinv, e3 * pinv };
    BP4 hp, lp;
#pragma unroll
    for (int j = 0; j < 4; j++) {
        hp.b[j] = __float2bfloat16_rn(pv[j]);
        lp.b[j] = __float2bfloat16_rn(pv[j] - __bfloat162float(hp.b[j]));
    }
    __nv_bfloat16* rb = (__nv_bfloat16*)rp;     // row = 2048 bf16 slots
    *(uint2*)(rb + tid * 4)        = hp.u;      // P_hi first half
    *(uint2*)(rb + 1024 + tid * 4) = lp.u;      // P_lo second half
}

// ============================================================================
extern "C" void kernel_launch(void* const* d_in, const int* in_sizes, int n_in,
                              void* d_out, int out_size) {
    const float* x  = (const float*)d_in[0];
    const float* Wq = (const float*)d_in[1];
    const float* bq = (const float*)d_in[2];
    const float* Wk = (const float*)d_in[3];
    const float* bk = (const float*)d_in[4];
    const float* Wv = (const float*)d_in[5];
    const float* bv = (const float*)d_in[6];
    float* out = (float*)d_out;

    void *axh, *axl, *awth, *awtl, *aqh, *aql, *akh, *akl, *avth, *avtl, *as, *av;
    cudaGetSymbolAddress(&axh, g_xh);   cudaGetSymbolAddress(&axl, g_xl);
    cudaGetSymbolAddress(&awth, g_wth); cudaGetSymbolAddress(&awtl, g_wtl);
    cudaGetSymbolAddress(&aqh, g_qh);   cudaGetSymbolAddress(&aql, g_ql);
    cudaGetSymbolAddress(&akh, g_kh);   cudaGetSymbolAddress(&akl, g_kl);
    cudaGetSymbolAddress(&avth, g_vth); cudaGetSymbolAddress(&avtl, g_vtl);
    cudaGetSymbolAddress(&as, g_s);     cudaGetSymbolAddress(&av, g_v);

    cudaFuncSetAttribute(gemm3_mma<4, 256, 1>,
                         cudaFuncAttributeMaxDynamicSharedMemorySize, GSM_BYTES);
    cudaFuncSetAttribute(gemm3_mma<4, 1024, 0>,
                         cudaFuncAttributeMaxDynamicSharedMemorySize, GSM_BYTES);
    cudaFuncSetAttribute(gemm3_mma<16, 256, 0>,
                         cudaFuncAttributeMaxDynamicSharedMemorySize, GSM_BYTES);

    // 1. split inputs
    split_x_kernel<<<16384, 256>>>(x);
    splitT_w_kernel<<<dim3(4, 4, 3), 256>>>(Wq, Wk, Wv);

    // 2. QKV projection (bf16x3 HMMA): writes qh/ql, kh/kl, v
    gemm3_mma<4, 256, 1><<<dim3(512, 2, 3), 256, GSM_BYTES>>>(
        (const __nv_bfloat16*)axh, (const __nv_bfloat16*)axl,
        (const __nv_bfloat16*)awth, (const __nv_bfloat16*)awtl,
        (float*)av, bq, bk, bv,
        0LL, 65536LL, 0LL, 256, 256);

    // 3. v -> vT hi/lo
    conv_vT_kernel<<<dim3(16, 4, 64), 256>>>();

    // 4. scores = q @ k^T (bf16x3, fp32 out)
    gemm3_mma<4, 1024, 0><<<dim3(8, 8, 64), 256, GSM_BYTES>>>(
        (const __nv_bfloat16*)aqh, (const __nv_bfloat16*)aql,
        (const __nv_bfloat16*)akh, (const __nv_bfloat16*)akl,
        (float*)as, nullptr, nullptr, nullptr,
        262144LL, 262144LL, 1048576LL, 256, 256);

    // 5. softmax + normalize + split (in place)
    softmax_kernel<<<65536, 256>>>((float*)as);

    // 6. ctx = P @ v (bf16x3) -> out
    gemm3_mma<16, 256, 0><<<dim3(8, 2, 64), 256, GSM_BYTES>>>(
        (const __nv_bfloat16*)as, (const __nv_bfloat16*)as + 1024,
        (const __nv_bfloat16*)avth, (const __nv_bfloat16*)avtl,
        out, nullptr, nullptr, nullptr,
        2097152LL, 262144LL, 262144LL, 2048, 1024);
}